// round 1
// baseline (speedup 1.0000x reference)
#include <cuda_runtime.h>

#define WD 128
#define HT 128
#define NB 8
#define NC 16
#define HW (HT*WD)
#define CHW (NC*HT*WD)
#define HO 127
#define WO 127

// Scratch: 4 tap-planes Y_f[b][i][j], SoA. 4*8*128*128*4B = 8 MB.
__device__ float g_Y[4][NB][HT][WD];

__global__ void __launch_bounds__(256) kan_eval_kernel(
    const float* __restrict__ x,
    const float* __restrict__ base_weight,
    const float* __restrict__ spline_weight,
    const float* __restrict__ spline_scaler,
    const float* __restrict__ grid)
{
    // Padded, per-lane-replicated scaled spline weight table.
    // Row p corresponds to basis j = p-3 (zero outside j in [0,8)); rows 14..17
    // are the all-zero rows used for out-of-range inputs.
    // Layout tab[p*32 + lane] -> conflict-free LDS.128 gathers.
    __shared__ float4 tab[18 * 32];

    const int tid = threadIdx.x;
    for (int e = tid; e < 18 * 32; e += 256) {
        int p = e >> 5;
        int j = p - 3;
        float4 val = make_float4(0.f, 0.f, 0.f, 0.f);
        if (j >= 0 && j < 8) {
            val.x = spline_weight[0 * 8 + j] * spline_scaler[0];
            val.y = spline_weight[1 * 8 + j] * spline_scaler[1];
            val.z = spline_weight[2 * 8 + j] * spline_scaler[2];
            val.w = spline_weight[3 * 8 + j] * spline_scaler[3];
        }
        tab[e] = val;
    }
    __syncthreads();

    const float bw0 = __ldg(base_weight + 0);
    const float bw1 = __ldg(base_weight + 1);
    const float bw2 = __ldg(base_weight + 2);
    const float bw3 = __ldg(base_weight + 3);
    const float g0  = __ldg(grid + 0);
    const float invh = 1.0f / (__ldg(grid + 1) - g0);

    const int n = blockIdx.x * 256 + tid;
    const int j = n & (WD - 1);
    const int i = (n >> 7) & (HT - 1);
    const int b = n >> 14;
    const int lane = tid & 31;

    const float* xp = x + b * CHW + i * WD + j;

    float a0 = 0.f, a1 = 0.f, a2 = 0.f, a3 = 0.f;

#pragma unroll
    for (int c = 0; c < NC; c++) {
        const float v = __ldg(xp + c * HW);

        // Cell index + local coordinate on the (uniform) extended knot grid.
        const float p = (v - g0) * invh;
        const float fc = floorf(p);
        const float u = p - fc;
        const int cell = (int)fc;
        // valid cells are 0..10 (11 intervals over 12 knots); else -> zero rows
        const int cb = ((unsigned)cell <= 10u) ? cell : 14;

        // Uniform cubic B-spline blending weights (already /6).
        const float u2 = u * u;
        const float u3 = u2 * u;
        const float w0 = fmaf(fmaf(fmaf(-(1.f / 6.f), u, 0.5f), u, -0.5f), u, 1.f / 6.f);
        const float w1 = fmaf(0.5f, u3, 2.f / 3.f) - u2;
        const float w2 = fmaf(-0.5f, u3, fmaf(0.5f, u2, fmaf(0.5f, u, 1.f / 6.f)));
        const float w3 = u3 * (1.f / 6.f);

        // SiLU base path
        const float s = __fdividef(v, 1.f + __expf(-v));
        a0 = fmaf(s, bw0, a0);
        a1 = fmaf(s, bw1, a1);
        a2 = fmaf(s, bw2, a2);
        a3 = fmaf(s, bw3, a3);

        // Gather the 4 active basis rows (float4 over the 4 tap features).
        const float4* tp = tab + cb * 32 + lane;
        const float4 c0 = tp[0];
        const float4 c1 = tp[32];
        const float4 c2 = tp[64];
        const float4 c3 = tp[96];

        a0 = fmaf(w0, c0.x, a0); a1 = fmaf(w0, c0.y, a1);
        a2 = fmaf(w0, c0.z, a2); a3 = fmaf(w0, c0.w, a3);
        a0 = fmaf(w1, c1.x, a0); a1 = fmaf(w1, c1.y, a1);
        a2 = fmaf(w1, c1.z, a2); a3 = fmaf(w1, c1.w, a3);
        a0 = fmaf(w2, c2.x, a0); a1 = fmaf(w2, c2.y, a1);
        a2 = fmaf(w2, c2.z, a2); a3 = fmaf(w2, c2.w, a3);
        a0 = fmaf(w3, c3.x, a0); a1 = fmaf(w3, c3.y, a1);
        a2 = fmaf(w3, c3.z, a2); a3 = fmaf(w3, c3.w, a3);
    }

    const int off = b * HW + i * WD + j;
    (&g_Y[0][0][0][0])[off]          = a0;
    (&g_Y[1][0][0][0])[off]          = a1;
    (&g_Y[2][0][0][0])[off]          = a2;
    (&g_Y[3][0][0][0])[off]          = a3;
}

__global__ void kan_combine_kernel(float* __restrict__ out)
{
    const int wo = blockIdx.x * blockDim.x + threadIdx.x;
    const int ho = blockIdx.y * blockDim.y + threadIdx.y;
    const int b  = blockIdx.z;
    if (wo >= WO || ho >= HO) return;

    const float r =
        g_Y[0][b][ho][wo] +
        g_Y[1][b][ho][wo + 1] +
        g_Y[2][b][ho + 1][wo] +
        g_Y[3][b][ho + 1][wo + 1];

    out[(b * HO + ho) * WO + wo] = r;
}

extern "C" void kernel_launch(void* const* d_in, const int* in_sizes, int n_in,
                              void* d_out, int out_size)
{
    const float* x  = (const float*)d_in[0];
    const float* bw = (const float*)d_in[1];
    const float* sw = (const float*)d_in[2];
    const float* ss = (const float*)d_in[3];
    const float* gr = (const float*)d_in[4];
    float* out = (float*)d_out;

    (void)in_sizes; (void)n_in; (void)out_size;

    // K1: per-pixel spline eval, channel-summed tap planes
    kan_eval_kernel<<<(NB * HT * WD) / 256, 256>>>(x, bw, sw, ss, gr);

    // K2: 2x2 shift-add combine
    dim3 bs(128, 2, 1);
    dim3 gs(1, (HO + 1) / 2, NB);
    kan_combine_kernel<<<gs, bs>>>(out);
}